// round 13
// baseline (speedup 1.0000x reference)
#include <cuda_runtime.h>
#include <cuda_fp16.h>
#include <cstdint>

#define D_MODEL 2048
#define NUM_EXPERTS 64
#define M_TILE 128
#define KC 32
#define T_CHUNKS (D_MODEL / KC)    // 64
#define NTHREADS 128
#define AS 40                       // row stride (halfs) = 80B, ldmatrix conflict-free
#define SLICE_LEV_BYTES (32 * AS * 2)          // 2560: one warp, one level
#define SLICE_BYTES (2 * SLICE_LEV_BYTES)      // 5120
#define STAGE_BYTES (4 * SLICE_BYTES)          // 20480
#define SMEM_BYTES (2 * STAGE_BYTES)           // 40960 (logits 36864 fits)
#define LSTRIDE 72

// B fragments pre-packed: idx = (((c*2 + ks)*2 + lev)*8 + nf)*32 + lane  (uint2)
//   n = nf*8 + lane/4 ; k0 = c*32 + ks*16 + (lane&3)*2
__device__ __align__(16) uint2 g_wf[T_CHUNKS * 2 * 2 * 8 * 32];

__global__ void prep_w(const float* __restrict__ w) {
    const int idx = blockIdx.x * blockDim.x + threadIdx.x;   // 65536
    const int lane = idx & 31;
    const int nf   = (idx >> 5) & 7;
    const int lev  = (idx >> 8) & 1;
    const int ks   = (idx >> 9) & 1;
    const int c    = idx >> 10;

    const int n  = nf * 8 + (lane >> 2);
    const int k0 = c * KC + ks * 16 + (lane & 3) * 2;

    const float* row = w + (size_t)n * D_MODEL;
    float2 va = *reinterpret_cast<const float2*>(row + k0);
    float2 vb = *reinterpret_cast<const float2*>(row + k0 + 8);

    float v[4] = {va.x, va.y, vb.x, vb.y};
    __half h[4];
#pragma unroll
    for (int j = 0; j < 4; j++) {
        __half h0 = __float2half_rn(v[j]);
        h[j] = lev ? __float2half_rn(v[j] - __half2float(h0)) : h0;
    }
    __half2 lo = __halves2half2(h[0], h[1]);
    __half2 hi = __halves2half2(h[2], h[3]);
    uint2 o;
    o.x = *reinterpret_cast<uint32_t*>(&lo);
    o.y = *reinterpret_cast<uint32_t*>(&hi);
    g_wf[idx] = o;
}

__device__ __forceinline__ uint32_t smem_u32(const void* p) {
    uint32_t a;
    asm("{ .reg .u64 t; cvta.to.shared.u64 t, %1; cvt.u32.u64 %0, t; }" : "=r"(a) : "l"(p));
    return a;
}
__device__ __forceinline__ void ldmatrix_x4(uint32_t* r, uint32_t addr) {
    asm volatile("ldmatrix.sync.aligned.m8n8.x4.shared.b16 {%0,%1,%2,%3}, [%4];"
                 : "=r"(r[0]), "=r"(r[1]), "=r"(r[2]), "=r"(r[3]) : "r"(addr));
}
__device__ __forceinline__ void mma16816(float* d, const uint32_t* a, uint2 b) {
    asm volatile(
        "mma.sync.aligned.m16n8k16.row.col.f32.f16.f16.f32 "
        "{%0,%1,%2,%3}, {%4,%5,%6,%7}, {%8,%9}, {%0,%1,%2,%3};"
        : "+f"(d[0]), "+f"(d[1]), "+f"(d[2]), "+f"(d[3])
        : "r"(a[0]), "r"(a[1]), "r"(a[2]), "r"(a[3]), "r"(b.x), "r"(b.y));
}

__global__ void __launch_bounds__(NTHREADS, 2) router_mma(
    const float* __restrict__ x,
    const float* __restrict__ bias,
    float* __restrict__ out,
    int n_rows)
{
    extern __shared__ __align__(16) char smem[];
    const uint32_t sbase = smem_u32(smem);

    const int tid = threadIdx.x;
    const int wid = tid >> 5;          // 0..3, warp owns rows 32*wid..+31
    const int lane = tid & 31;
    const long long row0 = (long long)blockIdx.x * M_TILE;

    // x loader (per half of 16 rows): row = 16h + 4i + (lane>>3), col (lane&7)*4
    const int xri = lane >> 3;
    const int xc4 = (lane & 7) * 4;

    const float* xwb = x + (row0 + 32 * wid) * D_MODEL;
    const uint32_t wslice0 = sbase + wid * SLICE_BYTES;

    // acc[mt][nf][4]: rows 32*wid + 16*mt .., cols 8*nf ..
    float acc[2][8][4];
#pragma unroll
    for (int mt = 0; mt < 2; mt++)
#pragma unroll
        for (int nf = 0; nf < 8; nf++)
#pragma unroll
            for (int j = 0; j < 4; j++) acc[mt][nf][j] = 0.0f;

    float4 xv[4];

    auto loadg_half = [&](int c, int h) {
        const int k0 = c * KC;
#pragma unroll
        for (int i = 0; i < 4; i++)
            xv[i] = *reinterpret_cast<const float4*>(
                xwb + (long long)(16 * h + 4 * i + xri) * D_MODEL + k0 + xc4);
    };

    auto stores_half = [&](int buf, int h) {
        const uint32_t A0 = wslice0 + buf * STAGE_BYTES;
        const uint32_t A1 = A0 + SLICE_LEV_BYTES;
#pragma unroll
        for (int i = 0; i < 4; i++) {
            float4 v = xv[i];
            __half2 h0a = __floats2half2_rn(v.x, v.y);
            __half2 h0b = __floats2half2_rn(v.z, v.w);
            float r0 = v.x - __half2float(h0a.x);
            float r1 = v.y - __half2float(h0a.y);
            float r2 = v.z - __half2float(h0b.x);
            float r3 = v.w - __half2float(h0b.y);
            __half2 h1a = __floats2half2_rn(r0, r1);
            __half2 h1b = __floats2half2_rn(r2, r3);

            const uint32_t o = ((16 * h + 4 * i + xri) * AS + xc4) * 2;
            asm volatile("st.shared.v2.b32 [%0], {%1, %2};" ::
                "r"(A0 + o), "r"(*reinterpret_cast<uint32_t*>(&h0a)),
                "r"(*reinterpret_cast<uint32_t*>(&h0b)) : "memory");
            asm volatile("st.shared.v2.b32 [%0], {%1, %2};" ::
                "r"(A1 + o), "r"(*reinterpret_cast<uint32_t*>(&h1a)),
                "r"(*reinterpret_cast<uint32_t*>(&h1b)) : "memory");
        }
    };

    const int lrow = ((lane >> 3) & 1) * 8 + (lane & 7);
    const int lkof = (lane >> 4) * 8;

    auto compute_ks = [&](int c, int buf, int ks) {
        const uint32_t Ab = wslice0 + buf * STAGE_BYTES;
        // B frags: 16 uint2 (lev0: 0..7, lev1: 8..15)
        uint2 b[16];
        const uint2* Wf = g_wf + ((size_t)(c * 2 + ks) * 2) * 8 * 32;
#pragma unroll
        for (int q = 0; q < 16; q++)
            b[q] = Wf[q * 32 + lane];

        uint32_t a[2][4];   // [mt][4], one level at a time
        // lev0
#pragma unroll
        for (int mt = 0; mt < 2; mt++)
            ldmatrix_x4(a[mt], Ab + ((mt * 16 + lrow) * AS + ks * 16 + lkof) * 2);
#pragma unroll
        for (int mt = 0; mt < 2; mt++)
#pragma unroll
            for (int nf = 0; nf < 8; nf++)
                mma16816(acc[mt][nf], a[mt], b[nf]);           // x0*w0
#pragma unroll
        for (int mt = 0; mt < 2; mt++)
#pragma unroll
            for (int nf = 0; nf < 8; nf++)
                mma16816(acc[mt][nf], a[mt], b[8 + nf]);       // x0*w1
        // lev1
#pragma unroll
        for (int mt = 0; mt < 2; mt++)
            ldmatrix_x4(a[mt], Ab + SLICE_LEV_BYTES + ((mt * 16 + lrow) * AS + ks * 16 + lkof) * 2);
#pragma unroll
        for (int mt = 0; mt < 2; mt++)
#pragma unroll
            for (int nf = 0; nf < 8; nf++)
                mma16816(acc[mt][nf], a[mt], b[nf]);           // x1*w0
    };

    // ---- prologue (warp-local) ----
    loadg_half(0, 0);
    stores_half(0, 0);
    loadg_half(0, 1);
    stores_half(0, 1);
    __syncwarp();

    // ---- main loop: warp-independent, no CTA barrier ----
#pragma unroll 1
    for (int c = 0; c < T_CHUNKS; ++c) {
        const int buf = c & 1;
        const int cn = (c + 1 < T_CHUNKS) ? c + 1 : c;
        const int nbuf = (c + 1) & 1;

        loadg_half(cn, 0);
        compute_ks(c, buf, 0);
        if (c + 1 < T_CHUNKS) stores_half(nbuf, 0);
        loadg_half(cn, 1);
        compute_ks(c, buf, 1);
        if (c + 1 < T_CHUNKS) {
            stores_half(nbuf, 1);
            __syncwarp();
        }
    }

    // ---- epilogue ----
    __syncthreads();
    float* logits = reinterpret_cast<float*>(smem);
#pragma unroll
    for (int mt = 0; mt < 2; mt++)
#pragma unroll
        for (int nf = 0; nf < 8; nf++) {
            const int r = 32 * wid + 16 * mt + (lane >> 2);
            const int col = nf * 8 + (lane & 3) * 2;
            *reinterpret_cast<float2*>(logits + r * LSTRIDE + col) =
                make_float2(acc[mt][nf][0], acc[mt][nf][1]);
            *reinterpret_cast<float2*>(logits + (r + 8) * LSTRIDE + col) =
                make_float2(acc[mt][nf][2], acc[mt][nf][3]);
        }
    __syncthreads();

    {
        const int r = tid;   // 128 threads, 128 rows
        const float* lrw = logits + r * LSTRIDE;
        float v0 = -3.0e38f, v1 = -3.0e38f;
        int i0 = 0, i1 = 0;
#pragma unroll
        for (int e = 0; e < NUM_EXPERTS; e++) {
            float l = lrw[e] + __ldg(&bias[e]);
            if (l > v0) { v1 = v0; i1 = i0; v0 = l; i0 = e; }
            else if (l > v1) { v1 = l; i1 = e; }
        }
        float Z = 0.0f;
#pragma unroll
        for (int e = 0; e < NUM_EXPERTS; e++) {
            float l = lrw[e] + __ldg(&bias[e]);
            Z += __expf(l - v0);
        }
        float q0 = 1.0f / Z;
        float q1 = __expf(v1 - v0) / Z;
        float s = q0 + q1 + 1e-8f;
        long long gr = row0 + r;
        out[gr * 2 + 0] = q0 / s;
        out[gr * 2 + 1] = q1 / s;
        float* ido = out + (long long)n_rows * 2;
        ido[gr * 2 + 0] = (float)i0;
        ido[gr * 2 + 1] = (float)i1;
    }
}

extern "C" void kernel_launch(void* const* d_in, const int* in_sizes, int n_in,
                              void* d_out, int out_size) {
    const float* x    = (const float*)d_in[0];
    const float* gw   = (const float*)d_in[1];
    const float* bias = (const float*)d_in[2];
    float* out = (float*)d_out;
    int n_rows = in_sizes[0] / D_MODEL;   // 32768

    cudaFuncSetAttribute(router_mma, cudaFuncAttributeMaxDynamicSharedMemorySize, SMEM_BYTES);

    prep_w<<<(T_CHUNKS * 2 * 2 * 8 * 32) / 256, 256>>>(gw);
    router_mma<<<n_rows / M_TILE, NTHREADS, SMEM_BYTES>>>(x, bias, out, n_rows);
}

// round 14
// speedup vs baseline: 1.6860x; 1.6860x over previous
#include <cuda_runtime.h>
#include <cuda_fp16.h>
#include <cstdint>

#define D_MODEL 2048
#define NUM_EXPERTS 64
#define M_TILE 128
#define KC 32
#define T_CHUNKS (D_MODEL / KC)    // 64
#define NTHREADS 256
#define AS 40                       // row stride (halfs) = 80B, ldmatrix conflict-free
#define SLICE_LEV_BYTES (32 * AS * 2)        // 2560 : one m-group, one level
#define SLICE_BYTES (2 * SLICE_LEV_BYTES)    // 5120
#define STAGE_BYTES (4 * SLICE_BYTES)        // 20480
#define SMEM_BYTES (2 * STAGE_BYTES)         // 40960 (logits 36864 fits)
#define LSTRIDE 72

// B fragments pre-packed (R10 layout): idx = ((((c*2+wn)*2+ks)*2+lev)*4+nf)*32+lane (uint2)
//   n = wn*32 + nf*8 + lane/4 ; k0 = c*32 + ks*16 + (lane&3)*2
__device__ __align__(16) uint2 g_wf[T_CHUNKS * 2 * 2 * 2 * 4 * 32];

__global__ void prep_w(const float* __restrict__ w) {
    const int idx = blockIdx.x * blockDim.x + threadIdx.x;   // 65536
    const int lane = idx & 31;
    const int nf   = (idx >> 5) & 3;
    const int lev  = (idx >> 7) & 1;
    const int ks   = (idx >> 8) & 1;
    const int wn   = (idx >> 9) & 1;
    const int c    = idx >> 10;

    const int n  = wn * 32 + nf * 8 + (lane >> 2);
    const int k0 = c * KC + ks * 16 + (lane & 3) * 2;

    const float* row = w + (size_t)n * D_MODEL;
    float2 va = *reinterpret_cast<const float2*>(row + k0);
    float2 vb = *reinterpret_cast<const float2*>(row + k0 + 8);

    float v[4] = {va.x, va.y, vb.x, vb.y};
    __half h[4];
#pragma unroll
    for (int j = 0; j < 4; j++) {
        __half h0 = __float2half_rn(v[j]);
        h[j] = lev ? __float2half_rn(v[j] - __half2float(h0)) : h0;
    }
    __half2 lo = __halves2half2(h[0], h[1]);
    __half2 hi = __halves2half2(h[2], h[3]);
    uint2 o;
    o.x = *reinterpret_cast<uint32_t*>(&lo);
    o.y = *reinterpret_cast<uint32_t*>(&hi);
    g_wf[idx] = o;
}

__device__ __forceinline__ uint32_t smem_u32(const void* p) {
    uint32_t a;
    asm("{ .reg .u64 t; cvta.to.shared.u64 t, %1; cvt.u32.u64 %0, t; }" : "=r"(a) : "l"(p));
    return a;
}
__device__ __forceinline__ void ldmatrix_x4(uint32_t* r, uint32_t addr) {
    asm volatile("ldmatrix.sync.aligned.m8n8.x4.shared.b16 {%0,%1,%2,%3}, [%4];"
                 : "=r"(r[0]), "=r"(r[1]), "=r"(r[2]), "=r"(r[3]) : "r"(addr));
}
__device__ __forceinline__ void mma_f32(float* d, const uint32_t* a, uint2 b) {
    asm volatile(
        "mma.sync.aligned.m16n8k16.row.col.f32.f16.f16.f32 "
        "{%0,%1,%2,%3}, {%4,%5,%6,%7}, {%8,%9}, {%0,%1,%2,%3};"
        : "+f"(d[0]), "+f"(d[1]), "+f"(d[2]), "+f"(d[3])
        : "r"(a[0]), "r"(a[1]), "r"(a[2]), "r"(a[3]), "r"(b.x), "r"(b.y));
}
__device__ __forceinline__ void mma_f16(uint32_t* d, const uint32_t* a, uint2 b) {
    asm volatile(
        "mma.sync.aligned.m16n8k16.row.col.f16.f16.f16.f16 "
        "{%0,%1}, {%2,%3,%4,%5}, {%6,%7}, {%0,%1};"
        : "+r"(d[0]), "+r"(d[1])
        : "r"(a[0]), "r"(a[1]), "r"(a[2]), "r"(a[3]), "r"(b.x), "r"(b.y));
}

__global__ void __launch_bounds__(NTHREADS, 2) router_mma(
    const float* __restrict__ x,
    const float* __restrict__ bias,
    float* __restrict__ out,
    int n_rows)
{
    extern __shared__ __align__(16) char smem[];
    const uint32_t sbase = smem_u32(smem);

    const int tid = threadIdx.x;
    const int wid = tid >> 5;
    const int lane = tid & 31;
    const int wm = wid & 3;        // m-group: rows 32*wm..+31
    const int wn = wid >> 2;       // n-group: experts 32*wn..+31
    const long long row0 = (long long)blockIdx.x * M_TILE;

    // x loader: each warp loads 16 rows (its wn half of the m-group slice)
    const int xri = lane >> 3;        // 0..3
    const int xc4 = (lane & 7) * 4;   // float col

    const float* xwb = x + (row0 + 32 * wm + 16 * wn) * D_MODEL;
    const uint32_t mslice0 = sbase + wm * SLICE_BYTES;   // stage 0 slice of this m-group

    // fp32 acc for x0*w0 ; fp16 acc for residual products
    float acc[2][4][4];
    uint32_t acch[2][4][2];
#pragma unroll
    for (int mt = 0; mt < 2; mt++)
#pragma unroll
        for (int nf = 0; nf < 4; nf++) {
#pragma unroll
            for (int j = 0; j < 4; j++) acc[mt][nf][j] = 0.0f;
            acch[mt][nf][0] = 0u;
            acch[mt][nf][1] = 0u;
        }

    float4 xv[4];

    auto loadg = [&](int c) {
        const int k0 = c * KC;
#pragma unroll
        for (int i = 0; i < 4; i++)
            xv[i] = *reinterpret_cast<const float4*>(
                xwb + (long long)(4 * i + xri) * D_MODEL + k0 + xc4);
    };

    auto stores = [&](int buf) {
        const uint32_t A0 = mslice0 + buf * STAGE_BYTES;
        const uint32_t A1 = A0 + SLICE_LEV_BYTES;
#pragma unroll
        for (int i = 0; i < 4; i++) {
            float4 v = xv[i];
            __half2 h0a = __floats2half2_rn(v.x, v.y);
            __half2 h0b = __floats2half2_rn(v.z, v.w);
            float r0 = v.x - __half2float(h0a.x);
            float r1 = v.y - __half2float(h0a.y);
            float r2 = v.z - __half2float(h0b.x);
            float r3 = v.w - __half2float(h0b.y);
            __half2 h1a = __floats2half2_rn(r0, r1);
            __half2 h1b = __floats2half2_rn(r2, r3);

            const uint32_t o = ((16 * wn + 4 * i + xri) * AS + xc4) * 2;  // bytes
            asm volatile("st.shared.v2.b32 [%0], {%1, %2};" ::
                "r"(A0 + o), "r"(*reinterpret_cast<uint32_t*>(&h0a)),
                "r"(*reinterpret_cast<uint32_t*>(&h0b)) : "memory");
            asm volatile("st.shared.v2.b32 [%0], {%1, %2};" ::
                "r"(A1 + o), "r"(*reinterpret_cast<uint32_t*>(&h1a)),
                "r"(*reinterpret_cast<uint32_t*>(&h1b)) : "memory");
        }
    };

    const int lrow = ((lane >> 3) & 1) * 8 + (lane & 7);
    const int lkof = (lane >> 4) * 8;

    auto compute = [&](int c, int buf) {
        const uint32_t Ab = mslice0 + buf * STAGE_BYTES;
#pragma unroll
        for (int ks = 0; ks < 2; ks++) {
            // B frags: 8 uint2 (lev0: 0..3, lev1: 4..7) for this warp's n32
            uint2 b[8];
            const uint2* Wf = g_wf + (((size_t)(c * 2 + wn) * 2 + ks) * 2) * 4 * 32;
#pragma unroll
            for (int q = 0; q < 8; q++)
                b[q] = Wf[q * 32 + lane];

            uint32_t a0[2][4], a1[2][4];
#pragma unroll
            for (int mt = 0; mt < 2; mt++) {
                const uint32_t ro = ((mt * 16 + lrow) * AS + ks * 16 + lkof) * 2;
                ldmatrix_x4(a0[mt], Ab + ro);
                ldmatrix_x4(a1[mt], Ab + SLICE_LEV_BYTES + ro);
            }

            // x0*w0 : fp32 acc
#pragma unroll
            for (int mt = 0; mt < 2; mt++)
#pragma unroll
                for (int nf = 0; nf < 4; nf++)
                    mma_f32(acc[mt][nf], a0[mt], b[nf]);
            // x0*w1 : fp16 acc
#pragma unroll
            for (int mt = 0; mt < 2; mt++)
#pragma unroll
                for (int nf = 0; nf < 4; nf++)
                    mma_f16(acch[mt][nf], a0[mt], b[4 + nf]);
            // x1*w0 : fp16 acc
#pragma unroll
            for (int mt = 0; mt < 2; mt++)
#pragma unroll
                for (int nf = 0; nf < 4; nf++)
                    mma_f16(acch[mt][nf], a1[mt], b[nf]);
        }
    };

    // ---- main loop: 1 CTA barrier per chunk (partner warps share A slices) ----
    loadg(0);
    stores(0);
    __syncthreads();

#pragma unroll 1
    for (int c = 0; c < T_CHUNKS; ++c) {
        if (c + 1 < T_CHUNKS) loadg(c + 1);
        compute(c, c & 1);
        if (c + 1 < T_CHUNKS) stores((c + 1) & 1);
        __syncthreads();
    }

    // ---- epilogue: merge fp16 residual acc into fp32, scatter, top-2 ----
    float* logits = reinterpret_cast<float*>(smem);
#pragma unroll
    for (int mt = 0; mt < 2; mt++)
#pragma unroll
        for (int nf = 0; nf < 4; nf++) {
            __half2 hlo = *reinterpret_cast<__half2*>(&acch[mt][nf][0]);
            __half2 hhi = *reinterpret_cast<__half2*>(&acch[mt][nf][1]);
            float f0 = acc[mt][nf][0] + __half2float(hlo.x);
            float f1 = acc[mt][nf][1] + __half2float(hlo.y);
            float f2 = acc[mt][nf][2] + __half2float(hhi.x);
            float f3 = acc[mt][nf][3] + __half2float(hhi.y);
            const int r = 32 * wm + 16 * mt + (lane >> 2);
            const int col = 32 * wn + nf * 8 + (lane & 3) * 2;
            *reinterpret_cast<float2*>(logits + r * LSTRIDE + col) = make_float2(f0, f1);
            *reinterpret_cast<float2*>(logits + (r + 8) * LSTRIDE + col) = make_float2(f2, f3);
        }
    __syncthreads();

    if (tid < M_TILE) {
        const int r = tid;
        const float* lrw = logits + r * LSTRIDE;
        float v0 = -3.0e38f, v1 = -3.0e38f;
        int i0 = 0, i1 = 0;
#pragma unroll
        for (int e = 0; e < NUM_EXPERTS; e++) {
            float l = lrw[e] + __ldg(&bias[e]);
            if (l > v0) { v1 = v0; i1 = i0; v0 = l; i0 = e; }
            else if (l > v1) { v1 = l; i1 = e; }
        }
        float Z = 0.0f;
#pragma unroll
        for (int e = 0; e < NUM_EXPERTS; e++) {
            float l = lrw[e] + __ldg(&bias[e]);
            Z += __expf(l - v0);
        }
        float q0 = 1.0f / Z;
        float q1 = __expf(v1 - v0) / Z;
        float s = q0 + q1 + 1e-8f;
        long long gr = row0 + r;
        out[gr * 2 + 0] = q0 / s;
        out[gr * 2 + 1] = q1 / s;
        float* ido = out + (long long)n_rows * 2;
        ido[gr * 2 + 0] = (float)i0;
        ido[gr * 2 + 1] = (float)i1;
    }
}

extern "C" void kernel_launch(void* const* d_in, const int* in_sizes, int n_in,
                              void* d_out, int out_size) {
    const float* x    = (const float*)d_in[0];
    const float* gw   = (const float*)d_in[1];
    const float* bias = (const float*)d_in[2];
    float* out = (float*)d_out;
    int n_rows = in_sizes[0] / D_MODEL;   // 32768

    cudaFuncSetAttribute(router_mma, cudaFuncAttributeMaxDynamicSharedMemorySize, SMEM_BYTES);

    prep_w<<<(T_CHUNKS * 2 * 2 * 2 * 4 * 32) / 256, 256>>>(gw);
    router_mma<<<n_rows / M_TILE, NTHREADS, SMEM_BYTES>>>(x, bias, out, n_rows);
}